// round 11
// baseline (speedup 1.0000x reference)
#include <cuda_runtime.h>
#include <cstdint>

#define W 131072
#define J 21
#define NB 20
#define BLOCK 256
#define GRID 2048
#define WPB (BLOCK / 32)
#define NWARP (GRID * WPB)                 // 16384 warps
#define CHUNK (W / NWARP)                  // 8 frames per warp (exact)

// weights folded with denominators
#define C_PROJ   (1.0f / 42.0f)
#define C_BONE   (1.0f / 20.0f)
#define C_SMOOTH (0.5f / 63.0f)
#define C_LIFT   (0.1f / 63.0f)

#define FULL 0xFFFFFFFFu

__device__ double g_acc;           // zero at load; last block resets each call
__device__ unsigned int g_count;   // wraps to 0 via atomicInc

__global__ __launch_bounds__(BLOCK)
void loss_kernel(const float* __restrict__ pose,   // [(W+1),3,J]
                 const float* __restrict__ cam,    // [W,2,3]
                 const float* __restrict__ p2d,    // [W,2,J]
                 const float* __restrict__ blen,   // [NB]
                 const float* __restrict__ lift,   // [W,3,NB]
                 const int*   __restrict__ bc,     // [NB,2]
                 const int*   __restrict__ lbc,    // [NB,2]
                 float* __restrict__ out)
{
    const int tid  = threadIdx.x;
    const int lane = tid & 31;
    const int wid  = tid >> 5;
    const int gw   = blockIdx.x * WPB + wid;
    const int f0   = gw * CHUNK;

    const bool jok = lane < J;
    const bool bok = lane < NB;

    int ch = 0, pa = 0, lch = 0, lpa = 0;
    float bl = 0.0f;
    if (bok) {
        ch  = bc[2 * lane];
        pa  = bc[2 * lane + 1];
        lch = lbc[2 * lane];
        lpa = lbc[2 * lane + 1];
        bl  = blen[lane];
    }
    // warp-uniform: lift connections coincide with bone connections?
    const bool same_conn = __all_sync(FULL, !bok || (lch == ch && lpa == pa));

    float acc = 0.0f;

    {
        // xs[0] = frame f0-1 (clamped), xs[1] = frame f0; xs[2..5] loaded per block of 4
        float xs[6], ys[6], zs[6];
        {
            const float* pA = pose + (size_t)f0 * 63;
            xs[1] = jok ? pA[lane]         : 0.0f;
            ys[1] = jok ? pA[J + lane]     : 0.0f;
            zs[1] = jok ? pA[2 * J + lane] : 0.0f;
            const float* pB = pose + (size_t)(f0 > 0 ? f0 - 1 : 0) * 63;
            xs[0] = jok ? pB[lane]         : 0.0f;
            ys[0] = jok ? pB[J + lane]     : 0.0f;
            zs[0] = jok ? pB[2 * J + lane] : 0.0f;
        }

        // frame-0 bone term (done once, by the warp owning frame 0)
        if (f0 == 0) {
            float dx = __shfl_sync(FULL, xs[1], ch) - __shfl_sync(FULL, xs[1], pa);
            float dy = __shfl_sync(FULL, ys[1], ch) - __shfl_sync(FULL, ys[1], pa);
            float dz = __shfl_sync(FULL, zs[1], ch) - __shfl_sync(FULL, zs[1], pa);
            float len = dx * dx + dy * dy + dz * dz;
            float e = len - bl;
            if (bok) acc += C_BONE * e * e;
        }

        #pragma unroll
        for (int it = 0; it < CHUNK; it += 4) {
            const int w = f0 + it;      // frames processed: w .. w+3

            // ======== batch ALL DRAM-latency loads for 4 frames ========
            #pragma unroll
            for (int k = 0; k < 4; k++) {
                const float* pf = pose + (size_t)(w + k + 1) * 63;
                xs[k + 2] = jok ? pf[lane]         : 0.0f;
                ys[k + 2] = jok ? pf[J + lane]     : 0.0f;
                zs[k + 2] = jok ? pf[2 * J + lane] : 0.0f;
            }
            float qx[4], qy[4];
            #pragma unroll
            for (int k = 0; k < 4; k++) {
                const float* q = p2d + (size_t)(w + k) * 42;
                qx[k] = jok ? q[lane]     : 0.0f;
                qy[k] = jok ? q[J + lane] : 0.0f;
            }
            float lx[4], ly[4], lz[4];
            #pragma unroll
            for (int k = 0; k < 4; k++) {
                const float* ld = lift + (size_t)(w + k) * 60;
                lx[k] = bok ? ld[lane]          : 0.0f;
                ly[k] = bok ? ld[NB + lane]     : 0.0f;
                lz[k] = bok ? ld[2 * NB + lane] : 0.0f;
            }

            // ======== compute 4 frames ========
            #pragma unroll
            for (int k = 0; k < 4; k++) {
                const float x1 = xs[k + 2], y1 = ys[k + 2], z1 = zs[k + 2];

                // projection (cam is uniform per warp; L1/L2 resident soon)
                const float2* c = (const float2*)(cam + (size_t)(w + k) * 6);
                float2 c0 = c[0], c1 = c[1], c2 = c[2];
                float px = c0.x * x1 + c0.y * y1 + c1.x * z1 - qx[k];
                float py = c1.y * x1 + c2.x * y1 + c2.y * z1 - qy[k];
                if (jok) acc += C_PROJ * (px * px + py * py);

                // smoothness: valid when processed frame index (w+k) >= 1
                if (w + k >= 1) {
                    float a0 = x1 - 2.0f * xs[k + 1] + xs[k];
                    float a1 = y1 - 2.0f * ys[k + 1] + ys[k];
                    float a2 = z1 - 2.0f * zs[k + 1] + zs[k];
                    if (jok) acc += C_SMOOTH * (a0 * a0 + a1 * a1 + a2 * a2);
                }

                // bone length (frame w+k+1)
                float bx = __shfl_sync(FULL, x1, ch) - __shfl_sync(FULL, x1, pa);
                float by = __shfl_sync(FULL, y1, ch) - __shfl_sync(FULL, y1, pa);
                float bz = __shfl_sync(FULL, z1, ch) - __shfl_sync(FULL, z1, pa);
                float len = bx * bx + by * by + bz * bz;
                float e = len - bl;
                if (bok) acc += C_BONE * e * e;

                // lift direction
                float ux, uy, uz;
                if (same_conn) { ux = bx; uy = by; uz = bz; }
                else {
                    ux = __shfl_sync(FULL, x1, lch) - __shfl_sync(FULL, x1, lpa);
                    uy = __shfl_sync(FULL, y1, lch) - __shfl_sync(FULL, y1, lpa);
                    uz = __shfl_sync(FULL, z1, lch) - __shfl_sync(FULL, z1, lpa);
                }
                float inv = bok ? (1.0f / sqrtf(ux * ux + uy * uy + uz * uz)) : 0.0f;
                float ex = lx[k] - ux * inv;
                float ey = ly[k] - uy * inv;
                float ez = lz[k] - uz * inv;
                if (bok) acc += C_LIFT * (ex * ex + ey * ey + ez * ez);
            }

            // rotate history for next block of 4
            xs[0] = xs[4]; ys[0] = ys[4]; zs[0] = zs[4];
            xs[1] = xs[5]; ys[1] = ys[5]; zs[1] = zs[5];
        }
    }

    // ---- warp reduction ----
    #pragma unroll
    for (int off = 16; off > 0; off >>= 1)
        acc += __shfl_down_sync(FULL, acc, off);

    __shared__ float warp_sums[WPB];
    __shared__ bool  is_last;
    if (lane == 0) warp_sums[wid] = acc;
    __syncthreads();

    if (wid == 0) {
        float v = (lane < WPB) ? warp_sums[lane] : 0.0f;
        #pragma unroll
        for (int off = 4; off > 0; off >>= 1)
            v += __shfl_down_sync(FULL, v, off);
        if (lane == 0) {
            atomicAdd(&g_acc, (double)v);
            __threadfence();
            unsigned int ticket = atomicInc(&g_count, GRID - 1);
            is_last = (ticket == GRID - 1);
        }
    }
    __syncthreads();

    if (is_last && tid == 0) {
        __threadfence();
        out[0] = (float)g_acc;
        g_acc = 0.0;   // reset for next graph replay (g_count already wrapped)
        __threadfence();
    }
}

extern "C" void kernel_launch(void* const* d_in, const int* in_sizes, int n_in,
                              void* d_out, int out_size)
{
    const float* pose = (const float*)d_in[0];
    const float* cam  = (const float*)d_in[1];
    const float* p2d  = (const float*)d_in[2];
    const float* blen = (const float*)d_in[3];
    const float* lift = (const float*)d_in[4];
    const int*   bc   = (const int*)d_in[5];
    const int*   lbc  = (const int*)d_in[6];
    float* out = (float*)d_out;

    loss_kernel<<<GRID, BLOCK>>>(pose, cam, p2d, blen, lift, bc, lbc, out);
}

// round 12
// speedup vs baseline: 1.2152x; 1.2152x over previous
#include <cuda_runtime.h>
#include <cstdint>

#define W 131072
#define J 21
#define NB 20
#define BLOCK 256
#define GRID 2048
#define WPB (BLOCK / 32)
#define NWARP (GRID * WPB)                 // 16384 warps
#define CHUNK (W / NWARP)                  // 8 frames per warp (exact)

// weights folded with denominators
#define C_PROJ   (1.0f / 42.0f)
#define C_BONE   (1.0f / 20.0f)
#define C_SMOOTH (0.5f / 63.0f)
#define C_LIFT   (0.1f / 63.0f)

#define FULL 0xFFFFFFFFu

__device__ double g_acc;           // zero at load; last block resets each call
__device__ unsigned int g_count;   // wraps to 0 via atomicInc

__global__ __launch_bounds__(BLOCK, 6)
void loss_kernel(const float* __restrict__ pose,   // [(W+1),3,J]
                 const float* __restrict__ cam,    // [W,2,3]
                 const float* __restrict__ p2d,    // [W,2,J]
                 const float* __restrict__ blen,   // [NB]
                 const float* __restrict__ lift,   // [W,3,NB]
                 const int*   __restrict__ bc,     // [NB,2]
                 const int*   __restrict__ lbc,    // [NB,2]
                 float* __restrict__ out)
{
    const int tid  = threadIdx.x;
    const int lane = tid & 31;
    const int wid  = tid >> 5;
    const int gw   = blockIdx.x * WPB + wid;
    const int f0   = gw * CHUNK;

    const bool jok = lane < J;
    const bool bok = lane < NB;

    int ch = 0, pa = 0, lch = 0, lpa = 0;
    float bl = 0.0f;
    if (bok) {
        ch  = bc[2 * lane];
        pa  = bc[2 * lane + 1];
        lch = lbc[2 * lane];
        lpa = lbc[2 * lane + 1];
        bl  = blen[lane];
    }
    // warp-uniform: lift connections coincide with bone connections?
    const bool same_conn = __all_sync(FULL, !bok || (lch == ch && lpa == pa));

    float acc = 0.0f;

    {
        // ---- lead-in: x0 = pose frame f0, xm = pose frame max(f0-1,0) ----
        const float* pA = pose + (size_t)f0 * 63;
        float x0 = jok ? pA[lane]          : 0.0f;
        float y0 = jok ? pA[J + lane]      : 0.0f;
        float z0 = jok ? pA[2 * J + lane]  : 0.0f;
        const float* pB = pose + (size_t)(f0 > 0 ? f0 - 1 : 0) * 63;
        float xm = jok ? pB[lane]          : 0.0f;
        float ym = jok ? pB[J + lane]      : 0.0f;
        float zm = jok ? pB[2 * J + lane]  : 0.0f;

        // frame-0 bone term (done once, by the warp owning frame 0)
        if (f0 == 0) {
            float dx = __shfl_sync(FULL, x0, ch) - __shfl_sync(FULL, x0, pa);
            float dy = __shfl_sync(FULL, y0, ch) - __shfl_sync(FULL, y0, pa);
            float dz = __shfl_sync(FULL, z0, ch) - __shfl_sync(FULL, z0, pa);
            float len = dx * dx + dy * dy + dz * dz;
            float e = len - bl;
            if (bok) acc += C_BONE * e * e;
        }

        #pragma unroll
        for (int it = 0; it < CHUNK; it += 2) {
            const int w = f0 + it;

            // ===== batch the DRAM-latency loads for both frames =====
            const float* pf1 = pose + (size_t)(w + 1) * 63;
            float x1 = jok ? pf1[lane]         : 0.0f;
            float y1 = jok ? pf1[J + lane]     : 0.0f;
            float z1 = jok ? pf1[2 * J + lane] : 0.0f;

            const float* pf2 = pose + (size_t)(w + 2) * 63;
            float x2 = jok ? pf2[lane]         : 0.0f;
            float y2 = jok ? pf2[J + lane]     : 0.0f;
            float z2 = jok ? pf2[2 * J + lane] : 0.0f;

            const float* qa = p2d + (size_t)w * 42;
            float qx1 = jok ? qa[lane]     : 0.0f;
            float qy1 = jok ? qa[J + lane] : 0.0f;
            const float* qb = qa + 42;
            float qx2 = jok ? qb[lane]     : 0.0f;
            float qy2 = jok ? qb[J + lane] : 0.0f;

            const float* la = lift + (size_t)w * 60;
            float lx1 = bok ? la[lane]          : 0.0f;
            float ly1 = bok ? la[NB + lane]     : 0.0f;
            float lz1 = bok ? la[2 * NB + lane] : 0.0f;
            const float* lb = la + 60;
            float lx2 = bok ? lb[lane]          : 0.0f;
            float ly2 = bok ? lb[NB + lane]     : 0.0f;
            float lz2 = bok ? lb[2 * NB + lane] : 0.0f;

            // ======== frame w (cam loaded here: uniform, L2-hot) ========
            {
                const float2* c = (const float2*)(cam + (size_t)w * 6);
                float2 c0 = c[0], c1 = c[1], c2 = c[2];
                float px = c0.x * x1 + c0.y * y1 + c1.x * z1 - qx1;
                float py = c1.y * x1 + c2.x * y1 + c2.y * z1 - qy1;
                if (jok) acc += C_PROJ * (px * px + py * py);

                if (w >= 1 || it > 0) {
                    float a0 = x1 - 2.0f * x0 + xm;
                    float a1 = y1 - 2.0f * y0 + ym;
                    float a2 = z1 - 2.0f * z0 + zm;
                    if (jok) acc += C_SMOOTH * (a0 * a0 + a1 * a1 + a2 * a2);
                }

                float bx = __shfl_sync(FULL, x1, ch) - __shfl_sync(FULL, x1, pa);
                float by = __shfl_sync(FULL, y1, ch) - __shfl_sync(FULL, y1, pa);
                float bz = __shfl_sync(FULL, z1, ch) - __shfl_sync(FULL, z1, pa);
                float len = bx * bx + by * by + bz * bz;
                float e = len - bl;
                if (bok) acc += C_BONE * e * e;

                float ux, uy, uz;
                if (same_conn) { ux = bx; uy = by; uz = bz; }
                else {
                    ux = __shfl_sync(FULL, x1, lch) - __shfl_sync(FULL, x1, lpa);
                    uy = __shfl_sync(FULL, y1, lch) - __shfl_sync(FULL, y1, lpa);
                    uz = __shfl_sync(FULL, z1, lch) - __shfl_sync(FULL, z1, lpa);
                }
                float inv = bok ? (1.0f / sqrtf(ux * ux + uy * uy + uz * uz)) : 0.0f;
                float ex = lx1 - ux * inv;
                float ey = ly1 - uy * inv;
                float ez = lz1 - uz * inv;
                if (bok) acc += C_LIFT * (ex * ex + ey * ey + ez * ez);
            }

            // ======== frame w+1 ========
            {
                const float2* c = (const float2*)(cam + (size_t)(w + 1) * 6);
                float2 c0 = c[0], c1 = c[1], c2 = c[2];
                float px = c0.x * x2 + c0.y * y2 + c1.x * z2 - qx2;
                float py = c1.y * x2 + c2.x * y2 + c2.y * z2 - qy2;
                if (jok) acc += C_PROJ * (px * px + py * py);

                float a0 = x2 - 2.0f * x1 + x0;
                float a1 = y2 - 2.0f * y1 + y0;
                float a2 = z2 - 2.0f * z1 + z0;
                if (jok) acc += C_SMOOTH * (a0 * a0 + a1 * a1 + a2 * a2);

                float bx = __shfl_sync(FULL, x2, ch) - __shfl_sync(FULL, x2, pa);
                float by = __shfl_sync(FULL, y2, ch) - __shfl_sync(FULL, y2, pa);
                float bz = __shfl_sync(FULL, z2, ch) - __shfl_sync(FULL, z2, pa);
                float len = bx * bx + by * by + bz * bz;
                float e = len - bl;
                if (bok) acc += C_BONE * e * e;

                float ux, uy, uz;
                if (same_conn) { ux = bx; uy = by; uz = bz; }
                else {
                    ux = __shfl_sync(FULL, x2, lch) - __shfl_sync(FULL, x2, lpa);
                    uy = __shfl_sync(FULL, y2, lch) - __shfl_sync(FULL, y2, lpa);
                    uz = __shfl_sync(FULL, z2, lch) - __shfl_sync(FULL, z2, lpa);
                }
                float inv = bok ? (1.0f / sqrtf(ux * ux + uy * uy + uz * uz)) : 0.0f;
                float ex = lx2 - ux * inv;
                float ey = ly2 - uy * inv;
                float ez = lz2 - uz * inv;
                if (bok) acc += C_LIFT * (ex * ex + ey * ey + ez * ez);
            }

            // rotate: after pair, prev = pose[w+1], cur = pose[w+2]
            xm = x1; ym = y1; zm = z1;
            x0 = x2; y0 = y2; z0 = z2;
        }
    }

    // ---- warp reduction ----
    #pragma unroll
    for (int off = 16; off > 0; off >>= 1)
        acc += __shfl_down_sync(FULL, acc, off);

    __shared__ float warp_sums[WPB];
    __shared__ bool  is_last;
    if (lane == 0) warp_sums[wid] = acc;
    __syncthreads();

    if (wid == 0) {
        float v = (lane < WPB) ? warp_sums[lane] : 0.0f;
        #pragma unroll
        for (int off = 4; off > 0; off >>= 1)
            v += __shfl_down_sync(FULL, v, off);
        if (lane == 0) {
            atomicAdd(&g_acc, (double)v);
            __threadfence();
            unsigned int ticket = atomicInc(&g_count, GRID - 1);
            is_last = (ticket == GRID - 1);
        }
    }
    __syncthreads();

    if (is_last && tid == 0) {
        __threadfence();
        out[0] = (float)g_acc;
        g_acc = 0.0;   // reset for next graph replay (g_count already wrapped)
        __threadfence();
    }
}

extern "C" void kernel_launch(void* const* d_in, const int* in_sizes, int n_in,
                              void* d_out, int out_size)
{
    const float* pose = (const float*)d_in[0];
    const float* cam  = (const float*)d_in[1];
    const float* p2d  = (const float*)d_in[2];
    const float* blen = (const float*)d_in[3];
    const float* lift = (const float*)d_in[4];
    const int*   bc   = (const int*)d_in[5];
    const int*   lbc  = (const int*)d_in[6];
    float* out = (float*)d_out;

    loss_kernel<<<GRID, BLOCK>>>(pose, cam, p2d, blen, lift, bc, lbc, out);
}